// round 10
// baseline (speedup 1.0000x reference)
#include <cuda_runtime.h>
#include <cuda_fp16.h>
#include <cstdint>

#define N_NODES   100000
#define N_EDGES   1600000
#define IN_FEATS  64
#define OUT_FEATS 32
#define NODE_PAIRS (N_NODES / 2)

// Scratch (no cudaMalloc allowed). hW stored as fp16 -> half the L2 traffic.
__device__ __half2 g_hW[N_NODES * OUT_FEATS / 2];   // 6.4 MB
__device__ float   g_deg[N_NODES];                  // 0.4 MB

__device__ __forceinline__ unsigned h2_as_u32(__half2 v) {
    return *reinterpret_cast<unsigned*>(&v);
}

// ---------------------------------------------------------------------------
// Kernel 1: fused  (a) zero d_out + g_deg,  (b) hW = h @ W  (fp32 math,
// fp16 store). 2-node x 8-feature tile, 128-thread blocks, 12 blocks/SM,
// explicit h prefetch.
// ---------------------------------------------------------------------------
__global__ void __launch_bounds__(128, 12) gemm_zero_kernel(
        const float* __restrict__ h,
        const float* __restrict__ W,
        float*       __restrict__ out) {
    __shared__ float4 sW4[IN_FEATS * OUT_FEATS / 4];   // 8 KB, natural [k][j]

    // stage W
    {
        const float4* W4 = reinterpret_cast<const float4*>(W);
        for (int i = threadIdx.x; i < IN_FEATS * OUT_FEATS / 4; i += blockDim.x)
            sW4[i] = W4[i];
    }

    // grid-stride zero of out (float4) and g_deg
    {
        int tg     = blockIdx.x * blockDim.x + threadIdx.x;
        int stride = gridDim.x * blockDim.x;
        float4 z = make_float4(0.f, 0.f, 0.f, 0.f);
        float4* out4 = reinterpret_cast<float4*>(out);
        for (int i = tg; i < N_NODES * OUT_FEATS / 4; i += stride)
            out4[i] = z;
        for (int i = tg; i < N_NODES; i += stride)
            g_deg[i] = 0.0f;
    }
    __syncthreads();

    int t  = blockIdx.x * blockDim.x + threadIdx.x;
    int np = t >> 2;            // node pair
    int jg = t & 3;             // 8-feature group
    if (np >= NODE_PAIRS) return;

    int node0 = np * 2;
    const float4* h0 = reinterpret_cast<const float4*>(h + (size_t)node0 * IN_FEATS);
    const float4* h1 = reinterpret_cast<const float4*>(h + (size_t)(node0 + 1) * IN_FEATS);

    float acc[2][8];
    #pragma unroll
    for (int i = 0; i < 2; i++)
        #pragma unroll
        for (int j = 0; j < 8; j++) acc[i][j] = 0.0f;

    float4 hv0 = __ldg(h0);
    float4 hv1 = __ldg(h1);

    #pragma unroll
    for (int k4 = 0; k4 < IN_FEATS / 4; k4++) {
        float4 cur0 = hv0, cur1 = hv1;
        if (k4 + 1 < IN_FEATS / 4) {
            hv0 = __ldg(h0 + k4 + 1);
            hv1 = __ldg(h1 + k4 + 1);
        }

        #pragma unroll
        for (int kk = 0; kk < 4; kk++) {
            int k = k4 * 4 + kk;
            float4 w0 = sW4[k * (OUT_FEATS / 4) + jg * 2 + 0];
            float4 w1 = sW4[k * (OUT_FEATS / 4) + jg * 2 + 1];
            float hk0 = (kk == 0) ? cur0.x : (kk == 1) ? cur0.y
                      : (kk == 2) ? cur0.z : cur0.w;
            float hk1 = (kk == 0) ? cur1.x : (kk == 1) ? cur1.y
                      : (kk == 2) ? cur1.z : cur1.w;

            acc[0][0] = fmaf(hk0, w0.x, acc[0][0]);
            acc[0][1] = fmaf(hk0, w0.y, acc[0][1]);
            acc[0][2] = fmaf(hk0, w0.z, acc[0][2]);
            acc[0][3] = fmaf(hk0, w0.w, acc[0][3]);
            acc[0][4] = fmaf(hk0, w1.x, acc[0][4]);
            acc[0][5] = fmaf(hk0, w1.y, acc[0][5]);
            acc[0][6] = fmaf(hk0, w1.z, acc[0][6]);
            acc[0][7] = fmaf(hk0, w1.w, acc[0][7]);

            acc[1][0] = fmaf(hk1, w0.x, acc[1][0]);
            acc[1][1] = fmaf(hk1, w0.y, acc[1][1]);
            acc[1][2] = fmaf(hk1, w0.z, acc[1][2]);
            acc[1][3] = fmaf(hk1, w0.w, acc[1][3]);
            acc[1][4] = fmaf(hk1, w1.x, acc[1][4]);
            acc[1][5] = fmaf(hk1, w1.y, acc[1][5]);
            acc[1][6] = fmaf(hk1, w1.z, acc[1][6]);
            acc[1][7] = fmaf(hk1, w1.w, acc[1][7]);
        }
    }

    // store 8 features as 4 half2 = one uint4 per node
    #pragma unroll
    for (int i = 0; i < 2; i++) {
        uint4 v;
        v.x = h2_as_u32(__floats2half2_rn(acc[i][0], acc[i][1]));
        v.y = h2_as_u32(__floats2half2_rn(acc[i][2], acc[i][3]));
        v.z = h2_as_u32(__floats2half2_rn(acc[i][4], acc[i][5]));
        v.w = h2_as_u32(__floats2half2_rn(acc[i][6], acc[i][7]));
        *reinterpret_cast<uint4*>(
            g_hW + (size_t)(node0 + i) * (OUT_FEATS / 2) + jg * 4) = v;
    }
}

// ---------------------------------------------------------------------------
// Kernel 2: edge scatter. 4 lanes per edge; each lane LDG.128 loads 8 halves
// (edge row = 64B total), converts to fp32, scales, 2x red.global.add.v4.f32.
// ---------------------------------------------------------------------------
__global__ void __launch_bounds__(256) scatter_kernel(
        const int*   __restrict__ src,
        const int*   __restrict__ dst,
        const float* __restrict__ order,
        float*       __restrict__ agg) {
    int t   = blockIdx.x * blockDim.x + threadIdx.x;
    int e   = t >> 2;        // edge
    int sub = t & 3;         // 8-feature slice
    if (e >= N_EDGES) return;

    int   s = __ldg(src + e);
    int   d = __ldg(dst + e);
    float w = __ldg(order + e);

    uint4 raw = __ldg(reinterpret_cast<const uint4*>(
                          g_hW + (size_t)s * (OUT_FEATS / 2) + sub * 4));

    __half2 q0 = *reinterpret_cast<__half2*>(&raw.x);
    __half2 q1 = *reinterpret_cast<__half2*>(&raw.y);
    __half2 q2 = *reinterpret_cast<__half2*>(&raw.z);
    __half2 q3 = *reinterpret_cast<__half2*>(&raw.w);

    float2 f0 = __half22float2(q0);
    float2 f1 = __half22float2(q1);
    float2 f2 = __half22float2(q2);
    float2 f3 = __half22float2(q3);

    float* a = agg + (size_t)d * OUT_FEATS + sub * 8;
    asm volatile("red.global.add.v4.f32 [%0], {%1, %2, %3, %4};"
                 :: "l"(a),
                    "f"(f0.x * w), "f"(f0.y * w), "f"(f1.x * w), "f"(f1.y * w)
                 : "memory");
    asm volatile("red.global.add.v4.f32 [%0], {%1, %2, %3, %4};"
                 :: "l"(a + 4),
                    "f"(f2.x * w), "f"(f2.y * w), "f"(f3.x * w), "f"(f3.y * w)
                 : "memory");

    if (sub == 0)
        atomicAdd(g_deg + d, 1.0f);
}

// ---------------------------------------------------------------------------
// Kernel 3: out = relu(agg/max(deg,1) + b), in place, float4-vectorized.
// ---------------------------------------------------------------------------
__global__ void __launch_bounds__(256) finalize_kernel(
        float* __restrict__ out,
        const float* __restrict__ b) {
    int t = blockIdx.x * blockDim.x + threadIdx.x;   // float4 index
    if (t >= N_NODES * OUT_FEATS / 4) return;
    int n  = t >> 3;   // node
    int j4 = t & 7;    // float4 within row

    float  deg  = __ldg(g_deg + n);
    float  norm = 1.0f / fmaxf(deg, 1.0f);
    float4 bb   = __ldg(reinterpret_cast<const float4*>(b) + j4);

    float4* out4 = reinterpret_cast<float4*>(out);
    float4 v = out4[t];
    v.x = fmaxf(fmaf(v.x, norm, bb.x), 0.0f);
    v.y = fmaxf(fmaf(v.y, norm, bb.y), 0.0f);
    v.z = fmaxf(fmaf(v.z, norm, bb.z), 0.0f);
    v.w = fmaxf(fmaf(v.w, norm, bb.w), 0.0f);
    out4[t] = v;
}

// ---------------------------------------------------------------------------
// Launch
// ---------------------------------------------------------------------------
extern "C" void kernel_launch(void* const* d_in, const int* in_sizes, int n_in,
                              void* d_out, int out_size) {
    const float* h     = (const float*)d_in[0];
    const int*   src   = (const int*)  d_in[1];
    const int*   dst   = (const int*)  d_in[2];
    const float* order = (const float*)d_in[3];
    const float* W     = (const float*)d_in[4];
    const float* b     = (const float*)d_in[5];
    float*       out   = (float*)d_out;

    (void)in_sizes; (void)n_in; (void)out_size;

    {
        long long total = (long long)NODE_PAIRS * 4;   // 200K threads
        int blocks = (int)((total + 127) / 128);
        gemm_zero_kernel<<<blocks, 128>>>(h, W, out);
    }

    {
        long long total = (long long)N_EDGES * 4;      // 4 lanes per edge
        int blocks = (int)((total + 255) / 256);
        scatter_kernel<<<blocks, 256>>>(src, dst, order, out);
    }

    finalize_kernel<<<(N_NODES * OUT_FEATS / 4 + 255) / 256, 256>>>(out, b);
}

// round 11
// speedup vs baseline: 1.2213x; 1.2213x over previous
#include <cuda_runtime.h>
#include <cuda_fp16.h>
#include <cstdint>

#define N_NODES   100000
#define N_EDGES   1600000
#define IN_FEATS  64
#define OUT_FEATS 32
#define NODE_PAIRS (N_NODES / 2)

// Scratch (no cudaMalloc allowed). hW stored as fp16 -> half the gather traffic.
__device__ __half2 g_hW[N_NODES * OUT_FEATS / 2];   // 6.4 MB
__device__ float   g_deg[N_NODES];                  // 0.4 MB

__device__ __forceinline__ unsigned h2_as_u32(__half2 v) {
    return *reinterpret_cast<unsigned*>(&v);
}

// ---------------------------------------------------------------------------
// Kernel 1: fused  (a) zero d_out + g_deg,  (b) hW = h @ W  (fp32 math,
// fp16 store). 2-node x 8-feature tile, 128-thread blocks, 12 blocks/SM,
// explicit h prefetch.
// ---------------------------------------------------------------------------
__global__ void __launch_bounds__(128, 12) gemm_zero_kernel(
        const float* __restrict__ h,
        const float* __restrict__ W,
        float*       __restrict__ out) {
    __shared__ float4 sW4[IN_FEATS * OUT_FEATS / 4];   // 8 KB, natural [k][j]

    // stage W
    {
        const float4* W4 = reinterpret_cast<const float4*>(W);
        for (int i = threadIdx.x; i < IN_FEATS * OUT_FEATS / 4; i += blockDim.x)
            sW4[i] = W4[i];
    }

    // grid-stride zero of out (float4) and g_deg
    {
        int tg     = blockIdx.x * blockDim.x + threadIdx.x;
        int stride = gridDim.x * blockDim.x;
        float4 z = make_float4(0.f, 0.f, 0.f, 0.f);
        float4* out4 = reinterpret_cast<float4*>(out);
        for (int i = tg; i < N_NODES * OUT_FEATS / 4; i += stride)
            out4[i] = z;
        for (int i = tg; i < N_NODES; i += stride)
            g_deg[i] = 0.0f;
    }
    __syncthreads();

    int t  = blockIdx.x * blockDim.x + threadIdx.x;
    int np = t >> 2;            // node pair
    int jg = t & 3;             // 8-feature group
    if (np >= NODE_PAIRS) return;

    int node0 = np * 2;
    const float4* h0 = reinterpret_cast<const float4*>(h + (size_t)node0 * IN_FEATS);
    const float4* h1 = reinterpret_cast<const float4*>(h + (size_t)(node0 + 1) * IN_FEATS);

    float acc[2][8];
    #pragma unroll
    for (int i = 0; i < 2; i++)
        #pragma unroll
        for (int j = 0; j < 8; j++) acc[i][j] = 0.0f;

    float4 hv0 = __ldg(h0);
    float4 hv1 = __ldg(h1);

    #pragma unroll
    for (int k4 = 0; k4 < IN_FEATS / 4; k4++) {
        float4 cur0 = hv0, cur1 = hv1;
        if (k4 + 1 < IN_FEATS / 4) {
            hv0 = __ldg(h0 + k4 + 1);
            hv1 = __ldg(h1 + k4 + 1);
        }

        #pragma unroll
        for (int kk = 0; kk < 4; kk++) {
            int k = k4 * 4 + kk;
            float4 w0 = sW4[k * (OUT_FEATS / 4) + jg * 2 + 0];
            float4 w1 = sW4[k * (OUT_FEATS / 4) + jg * 2 + 1];
            float hk0 = (kk == 0) ? cur0.x : (kk == 1) ? cur0.y
                      : (kk == 2) ? cur0.z : cur0.w;
            float hk1 = (kk == 0) ? cur1.x : (kk == 1) ? cur1.y
                      : (kk == 2) ? cur1.z : cur1.w;

            acc[0][0] = fmaf(hk0, w0.x, acc[0][0]);
            acc[0][1] = fmaf(hk0, w0.y, acc[0][1]);
            acc[0][2] = fmaf(hk0, w0.z, acc[0][2]);
            acc[0][3] = fmaf(hk0, w0.w, acc[0][3]);
            acc[0][4] = fmaf(hk0, w1.x, acc[0][4]);
            acc[0][5] = fmaf(hk0, w1.y, acc[0][5]);
            acc[0][6] = fmaf(hk0, w1.z, acc[0][6]);
            acc[0][7] = fmaf(hk0, w1.w, acc[0][7]);

            acc[1][0] = fmaf(hk1, w0.x, acc[1][0]);
            acc[1][1] = fmaf(hk1, w0.y, acc[1][1]);
            acc[1][2] = fmaf(hk1, w0.z, acc[1][2]);
            acc[1][3] = fmaf(hk1, w0.w, acc[1][3]);
            acc[1][4] = fmaf(hk1, w1.x, acc[1][4]);
            acc[1][5] = fmaf(hk1, w1.y, acc[1][5]);
            acc[1][6] = fmaf(hk1, w1.z, acc[1][6]);
            acc[1][7] = fmaf(hk1, w1.w, acc[1][7]);
        }
    }

    // store 8 features as 4 half2 = one uint4 per node
    #pragma unroll
    for (int i = 0; i < 2; i++) {
        uint4 v;
        v.x = h2_as_u32(__floats2half2_rn(acc[i][0], acc[i][1]));
        v.y = h2_as_u32(__floats2half2_rn(acc[i][2], acc[i][3]));
        v.z = h2_as_u32(__floats2half2_rn(acc[i][4], acc[i][5]));
        v.w = h2_as_u32(__floats2half2_rn(acc[i][6], acc[i][7]));
        *reinterpret_cast<uint4*>(
            g_hW + (size_t)(node0 + i) * (OUT_FEATS / 2) + jg * 4) = v;
    }
}

// ---------------------------------------------------------------------------
// Kernel 2: edge scatter. 8 lanes per edge (round-8 coalescing shape):
// each lane loads 4 halves (uint2, 8B), converts to fp32, scales, and issues
// ONE red.global.add.v4.f32 on its contiguous 16B slice of the dst row.
// Per-edge atomic footprint = one contiguous 128B line per instruction group.
// ---------------------------------------------------------------------------
__global__ void __launch_bounds__(256) scatter_kernel(
        const int*   __restrict__ src,
        const int*   __restrict__ dst,
        const float* __restrict__ order,
        float*       __restrict__ agg) {
    int t   = blockIdx.x * blockDim.x + threadIdx.x;
    int e   = t >> 3;        // edge
    int sub = t & 7;         // 4-float slice of the 32 features
    if (e >= N_EDGES) return;

    int   s = __ldg(src + e);
    int   d = __ldg(dst + e);
    float w = __ldg(order + e);

    // 4 halves for features [sub*4, sub*4+3]
    uint2 raw = __ldg(reinterpret_cast<const uint2*>(
                          g_hW + (size_t)s * (OUT_FEATS / 2) + sub * 2));
    __half2 q0 = *reinterpret_cast<__half2*>(&raw.x);
    __half2 q1 = *reinterpret_cast<__half2*>(&raw.y);
    float2 f0 = __half22float2(q0);
    float2 f1 = __half22float2(q1);

    float* a = agg + (size_t)d * OUT_FEATS + sub * 4;
    asm volatile("red.global.add.v4.f32 [%0], {%1, %2, %3, %4};"
                 :: "l"(a),
                    "f"(f0.x * w), "f"(f0.y * w), "f"(f1.x * w), "f"(f1.y * w)
                 : "memory");

    if (sub == 0)
        atomicAdd(g_deg + d, 1.0f);
}

// ---------------------------------------------------------------------------
// Kernel 3: out = relu(agg/max(deg,1) + b), in place, float4-vectorized.
// ---------------------------------------------------------------------------
__global__ void __launch_bounds__(256) finalize_kernel(
        float* __restrict__ out,
        const float* __restrict__ b) {
    int t = blockIdx.x * blockDim.x + threadIdx.x;   // float4 index
    if (t >= N_NODES * OUT_FEATS / 4) return;
    int n  = t >> 3;   // node
    int j4 = t & 7;    // float4 within row

    float  deg  = __ldg(g_deg + n);
    float  norm = 1.0f / fmaxf(deg, 1.0f);
    float4 bb   = __ldg(reinterpret_cast<const float4*>(b) + j4);

    float4* out4 = reinterpret_cast<float4*>(out);
    float4 v = out4[t];
    v.x = fmaxf(fmaf(v.x, norm, bb.x), 0.0f);
    v.y = fmaxf(fmaf(v.y, norm, bb.y), 0.0f);
    v.z = fmaxf(fmaf(v.z, norm, bb.z), 0.0f);
    v.w = fmaxf(fmaf(v.w, norm, bb.w), 0.0f);
    out4[t] = v;
}

// ---------------------------------------------------------------------------
// Launch
// ---------------------------------------------------------------------------
extern "C" void kernel_launch(void* const* d_in, const int* in_sizes, int n_in,
                              void* d_out, int out_size) {
    const float* h     = (const float*)d_in[0];
    const int*   src   = (const int*)  d_in[1];
    const int*   dst   = (const int*)  d_in[2];
    const float* order = (const float*)d_in[3];
    const float* W     = (const float*)d_in[4];
    const float* b     = (const float*)d_in[5];
    float*       out   = (float*)d_out;

    (void)in_sizes; (void)n_in; (void)out_size;

    {
        long long total = (long long)NODE_PAIRS * 4;   // 200K threads
        int blocks = (int)((total + 127) / 128);
        gemm_zero_kernel<<<blocks, 128>>>(h, W, out);
    }

    {
        long long total = (long long)N_EDGES * 8;      // 8 lanes per edge
        int blocks = (int)((total + 255) / 256);
        scatter_kernel<<<blocks, 256>>>(src, dst, order, out);
    }

    finalize_kernel<<<(N_NODES * OUT_FEATS / 4 + 255) / 256, 256>>>(out, b);
}

// round 12
// speedup vs baseline: 1.2570x; 1.0292x over previous
#include <cuda_runtime.h>
#include <cuda_fp16.h>
#include <cstdint>

#define N_NODES   100000
#define N_EDGES   1600000
#define IN_FEATS  64
#define OUT_FEATS 32
#define NODE_PAIRS (N_NODES / 2)

#define GEMM_BLOCKS  1563           // ceil(200000/128)
#define COUNT_BLOCKS 437            // histogram blocks appended to gemm grid

// Scratch (no cudaMalloc allowed)
__device__ __half2 g_hW[N_NODES * OUT_FEATS / 2];   // 6.4 MB, fp16 hW
__device__ int     g_cnt[N_NODES];                  // per-dst degree
__device__ int     g_off[N_NODES];                  // bin start
__device__ int     g_pos[N_NODES];                  // bin fill cursor
__device__ int     g_total;                         // global bin cursor
__device__ uint2   g_erec[N_EDGES];                 // binned (src, order)

__device__ __forceinline__ unsigned h2_as_u32(__half2 v) {
    return *reinterpret_cast<unsigned*>(&v);
}

// ---------------------------------------------------------------------------
// K0: zero histogram + cursor
// ---------------------------------------------------------------------------
__global__ void zero_cnt_kernel() {
    int i = blockIdx.x * blockDim.x + threadIdx.x;
    if (i < N_NODES) g_cnt[i] = 0;
    if (i == 0)      g_total = 0;
}

// ---------------------------------------------------------------------------
// K1: block-specialized: [0,GEMM_BLOCKS) -> hW = h @ W (fp32 math, fp16 store)
//                        [GEMM_BLOCKS,..) -> dst histogram (overlaps gemm)
// gemm body: 2-node x 8-feature tile, h prefetch (round-11 shape).
// ---------------------------------------------------------------------------
__global__ void __launch_bounds__(128, 12) gemm_count_kernel(
        const float* __restrict__ h,
        const float* __restrict__ W,
        const int*   __restrict__ dst) {
    if (blockIdx.x >= GEMM_BLOCKS) {
        int e0     = (blockIdx.x - GEMM_BLOCKS) * blockDim.x + threadIdx.x;
        int stride = COUNT_BLOCKS * blockDim.x;
        for (int e = e0; e < N_EDGES; e += stride)
            atomicAdd(g_cnt + __ldg(dst + e), 1);
        return;
    }

    __shared__ float4 sW4[IN_FEATS * OUT_FEATS / 4];   // 8 KB, [k][j]
    {
        const float4* W4 = reinterpret_cast<const float4*>(W);
        for (int i = threadIdx.x; i < IN_FEATS * OUT_FEATS / 4; i += blockDim.x)
            sW4[i] = W4[i];
    }
    __syncthreads();

    int t  = blockIdx.x * blockDim.x + threadIdx.x;
    int np = t >> 2;
    int jg = t & 3;
    if (np >= NODE_PAIRS) return;

    int node0 = np * 2;
    const float4* h0 = reinterpret_cast<const float4*>(h + (size_t)node0 * IN_FEATS);
    const float4* h1 = reinterpret_cast<const float4*>(h + (size_t)(node0 + 1) * IN_FEATS);

    float acc[2][8];
    #pragma unroll
    for (int i = 0; i < 2; i++)
        #pragma unroll
        for (int j = 0; j < 8; j++) acc[i][j] = 0.0f;

    float4 hv0 = __ldg(h0);
    float4 hv1 = __ldg(h1);

    #pragma unroll
    for (int k4 = 0; k4 < IN_FEATS / 4; k4++) {
        float4 cur0 = hv0, cur1 = hv1;
        if (k4 + 1 < IN_FEATS / 4) {
            hv0 = __ldg(h0 + k4 + 1);
            hv1 = __ldg(h1 + k4 + 1);
        }

        #pragma unroll
        for (int kk = 0; kk < 4; kk++) {
            int k = k4 * 4 + kk;
            float4 w0 = sW4[k * (OUT_FEATS / 4) + jg * 2 + 0];
            float4 w1 = sW4[k * (OUT_FEATS / 4) + jg * 2 + 1];
            float hk0 = (kk == 0) ? cur0.x : (kk == 1) ? cur0.y
                      : (kk == 2) ? cur0.z : cur0.w;
            float hk1 = (kk == 0) ? cur1.x : (kk == 1) ? cur1.y
                      : (kk == 2) ? cur1.z : cur1.w;

            acc[0][0] = fmaf(hk0, w0.x, acc[0][0]);
            acc[0][1] = fmaf(hk0, w0.y, acc[0][1]);
            acc[0][2] = fmaf(hk0, w0.z, acc[0][2]);
            acc[0][3] = fmaf(hk0, w0.w, acc[0][3]);
            acc[0][4] = fmaf(hk0, w1.x, acc[0][4]);
            acc[0][5] = fmaf(hk0, w1.y, acc[0][5]);
            acc[0][6] = fmaf(hk0, w1.z, acc[0][6]);
            acc[0][7] = fmaf(hk0, w1.w, acc[0][7]);

            acc[1][0] = fmaf(hk1, w0.x, acc[1][0]);
            acc[1][1] = fmaf(hk1, w0.y, acc[1][1]);
            acc[1][2] = fmaf(hk1, w0.z, acc[1][2]);
            acc[1][3] = fmaf(hk1, w0.w, acc[1][3]);
            acc[1][4] = fmaf(hk1, w1.x, acc[1][4]);
            acc[1][5] = fmaf(hk1, w1.y, acc[1][5]);
            acc[1][6] = fmaf(hk1, w1.z, acc[1][6]);
            acc[1][7] = fmaf(hk1, w1.w, acc[1][7]);
        }
    }

    #pragma unroll
    for (int i = 0; i < 2; i++) {
        uint4 v;
        v.x = h2_as_u32(__floats2half2_rn(acc[i][0], acc[i][1]));
        v.y = h2_as_u32(__floats2half2_rn(acc[i][2], acc[i][3]));
        v.z = h2_as_u32(__floats2half2_rn(acc[i][4], acc[i][5]));
        v.w = h2_as_u32(__floats2half2_rn(acc[i][6], acc[i][7]));
        *reinterpret_cast<uint4*>(
            g_hW + (size_t)(node0 + i) * (OUT_FEATS / 2) + jg * 4) = v;
    }
}

// ---------------------------------------------------------------------------
// K2: bin offsets via warp scan + one atomic cursor per warp.
// Bin ORDER is irrelevant for the gather, so no exact prefix scan needed.
// ---------------------------------------------------------------------------
__global__ void __launch_bounds__(256) offsets_kernel() {
    int i    = blockIdx.x * blockDim.x + threadIdx.x;
    int lane = threadIdx.x & 31;
    int cnt  = (i < N_NODES) ? g_cnt[i] : 0;

    // warp inclusive scan
    int incl = cnt;
    #pragma unroll
    for (int o = 1; o < 32; o <<= 1) {
        int v = __shfl_up_sync(0xFFFFFFFFu, incl, o);
        if (lane >= o) incl += v;
    }
    int excl = incl - cnt;

    int base = 0;
    if (lane == 31) base = atomicAdd(&g_total, incl);
    base = __shfl_sync(0xFFFFFFFFu, base, 31);

    if (i < N_NODES) {
        int o = base + excl;
        g_off[i] = o;
        g_pos[i] = o;
    }
}

// ---------------------------------------------------------------------------
// K3: reorder edges into dst bins: g_erec[pos] = (src, order_bits)
// ---------------------------------------------------------------------------
__global__ void __launch_bounds__(256) reorder_kernel(
        const int*   __restrict__ src,
        const int*   __restrict__ dst,
        const float* __restrict__ order) {
    int e = blockIdx.x * blockDim.x + threadIdx.x;
    if (e >= N_EDGES) return;
    int d = __ldg(dst + e);
    int p = atomicAdd(g_pos + d, 1);
    g_erec[p] = make_uint2((unsigned)__ldg(src + e),
                           __float_as_uint(__ldg(order + e)));
}

// ---------------------------------------------------------------------------
// K4: gather + normalize + bias + relu. 8 lanes per dst node, each owning
// 4 features. fp16 gather (64B/edge across the 8 lanes), fp32 accumulation,
// no atomics, single float4 store.
// ---------------------------------------------------------------------------
__global__ void __launch_bounds__(256) gather_kernel(
        float*       __restrict__ out,
        const float* __restrict__ b) {
    int t   = blockIdx.x * blockDim.x + threadIdx.x;
    int g   = t >> 3;        // dst node
    int sub = t & 7;         // 4-feature slice
    if (g >= N_NODES) return;

    int start = __ldg(g_off + g);
    int cnt   = __ldg(g_cnt + g);
    int end   = start + cnt;

    float4 acc = make_float4(0.f, 0.f, 0.f, 0.f);
    int p = start;
    for (; p + 2 <= end; p += 2) {
        uint2 r0 = g_erec[p];
        uint2 r1 = g_erec[p + 1];
        uint2 a0 = __ldg(reinterpret_cast<const uint2*>(
                             g_hW + (size_t)r0.x * (OUT_FEATS / 2) + sub * 2));
        uint2 a1 = __ldg(reinterpret_cast<const uint2*>(
                             g_hW + (size_t)r1.x * (OUT_FEATS / 2) + sub * 2));
        float w0 = __uint_as_float(r0.y);
        float w1 = __uint_as_float(r1.y);
        float2 f00 = __half22float2(*reinterpret_cast<__half2*>(&a0.x));
        float2 f01 = __half22float2(*reinterpret_cast<__half2*>(&a0.y));
        float2 f10 = __half22float2(*reinterpret_cast<__half2*>(&a1.x));
        float2 f11 = __half22float2(*reinterpret_cast<__half2*>(&a1.y));
        acc.x = fmaf(w0, f00.x, acc.x); acc.y = fmaf(w0, f00.y, acc.y);
        acc.z = fmaf(w0, f01.x, acc.z); acc.w = fmaf(w0, f01.y, acc.w);
        acc.x = fmaf(w1, f10.x, acc.x); acc.y = fmaf(w1, f10.y, acc.y);
        acc.z = fmaf(w1, f11.x, acc.z); acc.w = fmaf(w1, f11.y, acc.w);
    }
    if (p < end) {
        uint2 r0 = g_erec[p];
        uint2 a0 = __ldg(reinterpret_cast<const uint2*>(
                             g_hW + (size_t)r0.x * (OUT_FEATS / 2) + sub * 2));
        float w0 = __uint_as_float(r0.y);
        float2 f00 = __half22float2(*reinterpret_cast<__half2*>(&a0.x));
        float2 f01 = __half22float2(*reinterpret_cast<__half2*>(&a0.y));
        acc.x = fmaf(w0, f00.x, acc.x); acc.y = fmaf(w0, f00.y, acc.y);
        acc.z = fmaf(w0, f01.x, acc.z); acc.w = fmaf(w0, f01.y, acc.w);
    }

    float norm = 1.0f / fmaxf((float)cnt, 1.0f);
    float4 bb  = __ldg(reinterpret_cast<const float4*>(b) + sub);

    float4 r;
    r.x = fmaxf(fmaf(acc.x, norm, bb.x), 0.0f);
    r.y = fmaxf(fmaf(acc.y, norm, bb.y), 0.0f);
    r.z = fmaxf(fmaf(acc.z, norm, bb.z), 0.0f);
    r.w = fmaxf(fmaf(acc.w, norm, bb.w), 0.0f);
    reinterpret_cast<float4*>(out)[(size_t)g * 8 + sub] = r;
}

// ---------------------------------------------------------------------------
// Launch
// ---------------------------------------------------------------------------
extern "C" void kernel_launch(void* const* d_in, const int* in_sizes, int n_in,
                              void* d_out, int out_size) {
    const float* h     = (const float*)d_in[0];
    const int*   src   = (const int*)  d_in[1];
    const int*   dst   = (const int*)  d_in[2];
    const float* order = (const float*)d_in[3];
    const float* W     = (const float*)d_in[4];
    const float* b     = (const float*)d_in[5];
    float*       out   = (float*)d_out;

    (void)in_sizes; (void)n_in; (void)out_size;

    zero_cnt_kernel<<<(N_NODES + 255) / 256, 256>>>();

    gemm_count_kernel<<<GEMM_BLOCKS + COUNT_BLOCKS, 128>>>(h, W, dst);

    offsets_kernel<<<(N_NODES + 255) / 256, 256>>>();

    reorder_kernel<<<(N_EDGES + 255) / 256, 256>>>(src, dst, order);

    gather_kernel<<<(N_NODES * 8 + 255) / 256, 256>>>(out, b);
}